// round 5
// baseline (speedup 1.0000x reference)
#include <cuda_runtime.h>

// DigitCaps dynamic routing, GB300 sm_103a — R5.
// B=64, I=4096, Din=8, N=10, D=16, 3 routing iterations.
//
// R5 vs R4 (125.7us):
//  - 2 independent 320-thread blocks per SM (32 b x 10 n each): barrier/LDS
//    phases of one block overlap the FMA phases of the other
//  - producer-side exp: 1 exp2 per thread per i (was 10 expf), consumer reads
//    Z(il-1) as a 10-LDS sum after the barrier; v pre-scaled by log2(e) so
//    logits live in log2 domain (g_blog too) -> exact softmax identity
//  - k_finish: 320 x 512, 16 slices -> ~2us
//  - k_pad no-op first so ncu -s 5 -c 1 captures k_pass<2>

#define B_ 64
#define I_ 4096
#define P_ 8
#define N_ 10
#define D_ 16
#define ND_ 160
#define THREADS 320              // 32 b x 10 n
#define OUT_ (B_ * ND_)          // 10240
#define L2E 1.4426950408889634f

// dynamic smem layout (floats)
#define SX_SZ (224 * 33)         // x staged [r=il*8+p][bb], stride 33
#define SW_SZ (2 * 1280)         // double-buffered W[i][n][p][d]
#define SE_SZ (2 * 352)          // double-buffered exps, [bb*11+n]
#define SMEM_BYTES ((SX_SZ + SW_SZ + SE_SZ) * 4)   // 42,624 B < 48K default

__device__ float g_part[(size_t)148 * OUT_];    // per-chunk partials, 6.1MB
__device__ float g_blog[(size_t)I_ * 640];      // log2-domain logits [i][bh*320+tid]
__device__ float g_v[OUT_];                     // squashed v
__device__ float g_pad;                         // pad-kernel sink

typedef unsigned long long ull;

static __device__ __forceinline__ ull pack2(float a, float b) {
    ull r; asm("mov.b64 %0, {%1,%2};" : "=l"(r) : "f"(a), "f"(b)); return r;
}
static __device__ __forceinline__ float2 unpack2(ull v) {
    float2 r; asm("mov.b64 {%0,%1}, %2;" : "=f"(r.x), "=f"(r.y) : "l"(v)); return r;
}
static __device__ __forceinline__ ull ffma2(ull a, ull b, ull c) {
    ull d; asm("fma.rn.f32x2 %0, %1, %2, %3;" : "=l"(d) : "l"(a), "l"(b), "l"(c)); return d;
}
static __device__ __forceinline__ ull fadd2(ull a, ull b) {
    ull d; asm("add.rn.f32x2 %0, %1, %2;" : "=l"(d) : "l"(a), "l"(b)); return d;
}

__global__ void k_pad() { g_pad = 0.0f; }

template <int PASS>
__global__ __launch_bounds__(THREADS, 2) void k_pass(const float* __restrict__ X,
                                                     const float* __restrict__ W) {
    extern __shared__ float smem[];
    float* s_x = smem;                // [r*33 + bb]
    float* s_w = smem + SX_SZ;        // 2 x 1280
    float* s_e = s_w + SW_SZ;         // 2 x 352

    int tid = threadIdx.x;
    int n = tid >> 5;                 // warp id = n (warp-uniform)
    int bb = tid & 31;                // lane = local batch
    int cb = blockIdx.x;              // i-chunk 0..147
    int bh = blockIdx.y;              // batch half 0..1
    int i0, ni;
    if (cb < 100) { i0 = cb * 28; ni = 28; }
    else          { i0 = 2800 + (cb - 100) * 27; ni = 27; }
    int bg = bh * 32 + bb;            // global batch

    // ---- stage x: ni*8 floats per local batch (L1 catches line reuse)
    int nr = ni * 8;
    for (int idx = tid; idx < nr * 32; idx += THREADS) {
        int r = idx >> 5;
        int b2 = idx & 31;
        s_x[r * 33 + b2] = X[(size_t)(bh * 32 + b2) * (I_ * P_) + i0 * P_ + r];
    }
    // ---- stage W(0): 4 floats/thread, coalesced
    *(float4*)(s_w + tid * 4) = *(const float4*)(W + (size_t)i0 * 1280 + tid * 4);

    // ---- v (pre-scaled by log2 e) in registers
    ull v2[8];
    if (PASS > 0) {
        const float4* vp = (const float4*)(g_v + bg * ND_ + n * D_);
#pragma unroll
        for (int j = 0; j < 4; j++) {
            float4 f = vp[j];
            v2[2 * j]     = pack2(f.x * L2E, f.y * L2E);
            v2[2 * j + 1] = pack2(f.z * L2E, f.w * L2E);
        }
    }
    __syncthreads();

    ull t2[8];
    ull sacc[8];
#pragma unroll
    for (int j = 0; j < 8; j++) sacc[j] = 0ULL;
    float e_prev = 0.f;

#pragma unroll 2
    for (int il = 0; il < ni; il++) {
        int cur = il & 1;

        // prefetch W(il+1) and (pass2) prior logit
        float4 wpf;
        bool wok = (il + 1 < ni);
        if (wok) wpf = *(const float4*)(W + (size_t)(i0 + il + 1) * 1280 + tid * 4);
        float gb = 0.f;
        if (PASS == 2) gb = g_blog[(size_t)(i0 + il) * 640 + bh * 320 + tid];

        // ---- consume stage il-1 (t2 still holds t(il-1); e(il-1) complete in s_e)
        if (il > 0) {
            if (PASS > 0) {
                const float* se = s_e + (1 - cur) * 352 + bb * 11;
                float Z = ((se[0] + se[1]) + (se[2] + se[3])) +
                          ((se[4] + se[5]) + (se[6] + se[7])) + (se[8] + se[9]);
                float c = __fdividef(e_prev, Z);
                ull cp = pack2(c, c);
#pragma unroll
                for (int j = 0; j < 8; j++) sacc[j] = ffma2(cp, t2[j], sacc[j]);
            } else {
#pragma unroll
                for (int j = 0; j < 8; j++) sacc[j] = fadd2(sacc[j], t2[j]);
            }
        }

        // ---- compute t(il): u[b, i, n, 0:16]
#pragma unroll
        for (int j = 0; j < 8; j++) t2[j] = 0ULL;
        {
            const float* wbase = s_w + cur * 1280 + n * 128;
#pragma unroll
            for (int p = 0; p < P_; p++) {
                float xv = s_x[(il * 8 + p) * 33 + bb];               // conflict-free
                ull xp = pack2(xv, xv);
                const ulonglong2* wv = (const ulonglong2*)(wbase + p * D_);  // bcast
#pragma unroll
                for (int q = 0; q < 4; q++) {
                    ulonglong2 w = wv[q];
                    t2[2 * q]     = ffma2(xp, w.x, t2[2 * q]);
                    t2[2 * q + 1] = ffma2(xp, w.y, t2[2 * q + 1]);
                }
            }
        }

        // ---- agreement + producer-side exp (log2 domain)
        if (PASS > 0) {
            ull aa = 0ULL;
#pragma unroll
            for (int j = 0; j < 8; j++) aa = ffma2(t2[j], v2[j], aa);
            float2 af = unpack2(aa);
            float bn = af.x + af.y + (PASS == 2 ? gb : 0.f);
            if (PASS == 1) g_blog[(size_t)(i0 + il) * 640 + bh * 320 + tid] = bn;
            float e = exp2f(bn);
            s_e[cur * 352 + bb * 11 + n] = e;
            e_prev = e;
        }
        if (wok) *(float4*)(s_w + (1 - cur) * 1280 + tid * 4) = wpf;

        __syncthreads();
    }

    // ---- epilogue: consume last stage
    if (PASS > 0) {
        const float* se = s_e + ((ni - 1) & 1) * 352 + bb * 11;
        float Z = ((se[0] + se[1]) + (se[2] + se[3])) +
                  ((se[4] + se[5]) + (se[6] + se[7])) + (se[8] + se[9]);
        float c = __fdividef(e_prev, Z);
        ull cp = pack2(c, c);
#pragma unroll
        for (int j = 0; j < 8; j++) sacc[j] = ffma2(cp, t2[j], sacc[j]);
    } else {
#pragma unroll
        for (int j = 0; j < 8; j++) sacc[j] = fadd2(sacc[j], t2[j]);
    }

    // ---- per-chunk partials (deterministic; depth-148 reduction in k_finish)
    float4* po = (float4*)(g_part + (size_t)cb * OUT_ + bg * ND_ + n * D_);
#pragma unroll
    for (int q = 0; q < 4; q++) {
        float2 f0 = unpack2(sacc[2 * q]);
        float2 f1 = unpack2(sacc[2 * q + 1]);
        if (PASS == 0) { f0.x *= 0.1f; f0.y *= 0.1f; f1.x *= 0.1f; f1.y *= 0.1f; }
        po[q] = make_float4(f0.x, f0.y, f1.x, f1.y);
    }
}

// 148-way reduction + squash. Grid 320 x 512: 16 slices (4x10 + 12x9 = 148),
// 32 outputs per block, coalesced, fixed order (deterministic).
template <bool FINAL>
__global__ __launch_bounds__(512) void k_finish(float* __restrict__ dout) {
    __shared__ float red[16][33];
    int tid = threadIdx.x;
    int s = tid >> 5;
    int ol = tid & 31;
    int o = blockIdx.x * 32 + ol;

    int start = (s < 4) ? s * 10 : 40 + (s - 4) * 9;
    int cnt = (s < 4) ? 10 : 9;
    const float* p = g_part + (size_t)start * OUT_ + o;
    float a0 = 0.f, a1 = 0.f, a2 = 0.f, a3 = 0.f;
    int k = 0;
    for (; k + 4 <= cnt; k += 4) {
        a0 += p[(size_t)(k + 0) * OUT_];
        a1 += p[(size_t)(k + 1) * OUT_];
        a2 += p[(size_t)(k + 2) * OUT_];
        a3 += p[(size_t)(k + 3) * OUT_];
    }
    for (; k < cnt; k++) a0 += p[(size_t)k * OUT_];
    red[s][ol] = (a0 + a1) + (a2 + a3);
    __syncthreads();

    if (s == 0) {
        float t0 = (red[0][ol] + red[1][ol]) + (red[2][ol] + red[3][ol]);
        float t1 = (red[4][ol] + red[5][ol]) + (red[6][ol] + red[7][ol]);
        float t2 = (red[8][ol] + red[9][ol]) + (red[10][ol] + red[11][ol]);
        float t3 = (red[12][ol] + red[13][ol]) + (red[14][ol] + red[15][ol]);
        float sv = (t0 + t1) + (t2 + t3);
        float sq = sv * sv;
        float scale = sq / ((1.f + sq) * sqrtf(sq + 1e-7f));
        float v = scale * sv;
        if (FINAL) dout[o] = v;
        else       g_v[o] = v;
    }
}

extern "C" void kernel_launch(void* const* d_in, const int* in_sizes, int n_in,
                              void* d_out, int out_size) {
    const float* X = (const float*)d_in[0];
    const float* W = (const float*)d_in[1];
    if (n_in >= 2 && in_sizes[0] != B_ * I_ * P_) {
        const float* tmp = X; X = W; W = tmp;
    }

    dim3 gp(148, 2);
    k_pad<<<1, 1>>>();                                   // aligns ncu -s 5 on k_pass<2>
    k_pass<0><<<gp, THREADS, SMEM_BYTES>>>(X, W);
    k_finish<false><<<320, 512>>>(nullptr);
    k_pass<1><<<gp, THREADS, SMEM_BYTES>>>(X, W);
    k_finish<false><<<320, 512>>>(nullptr);
    k_pass<2><<<gp, THREADS, SMEM_BYTES>>>(X, W);
    k_finish<true><<<320, 512>>>((float*)d_out);
}

// round 6
// speedup vs baseline: 1.2360x; 1.2360x over previous
#include <cuda_runtime.h>

// DigitCaps dynamic routing, GB300 sm_103a — R6.
// B=64, I=4096, Din=8, N=10, D=16, 3 routing iterations.
//
// R6 vs R5 (133us; k_pass L1TEX-wavefront-bound, W-broadcast = 52% of wf):
//  - lane = 16 bb x 2 dh (d-half split), BTILE=2 batches/thread:
//    W LDS.128 per warp-il halved (16 vs 32) for identical coverage
//  - x via 2xLDS.128/batch from [b][r] stride-236 (data-minimal 4-phase)
//  - per-lane-batch Z rows (32 distinct stride-11 rows, conflict-free);
//    d-sum / Z / blog exchanged via shfl_xor(16) - no extra barriers
//  - ex2.approx.f32 (R5's exp2f hit the slow accurate path)
//  - 2 independent 320-thread blocks/SM, 1 barrier per i

#define B_ 64
#define I_ 4096
#define P_ 8
#define N_ 10
#define D_ 16
#define ND_ 160
#define THREADS 320
#define OUT_ (B_ * ND_)          // 10240
#define L2E 1.4426950408889634f

#define SX_STRIDE 236
#define SX_SZ (32 * SX_STRIDE)   // 7552 floats
#define SW_SZ (2 * 1280)         // 2560
#define SE_SZ (2 * 352)          // 704
#define SMEM_BYTES ((SX_SZ + SW_SZ + SE_SZ) * 4)   // 43,264 B

__device__ float g_part[(size_t)148 * OUT_];    // per-chunk partials
__device__ float g_blog[(size_t)I_ * 640];      // log2-domain logits [i][n*64+bh*32+l]
__device__ float g_v[OUT_];                     // squashed v
__device__ float g_pad;

typedef unsigned long long ull;

static __device__ __forceinline__ ull pack2(float a, float b) {
    ull r; asm("mov.b64 %0, {%1,%2};" : "=l"(r) : "f"(a), "f"(b)); return r;
}
static __device__ __forceinline__ float2 unpack2(ull v) {
    float2 r; asm("mov.b64 {%0,%1}, %2;" : "=f"(r.x), "=f"(r.y) : "l"(v)); return r;
}
static __device__ __forceinline__ ull ffma2(ull a, ull b, ull c) {
    ull d; asm("fma.rn.f32x2 %0, %1, %2, %3;" : "=l"(d) : "l"(a), "l"(b), "l"(c)); return d;
}
static __device__ __forceinline__ ull fadd2(ull a, ull b) {
    ull d; asm("add.rn.f32x2 %0, %1, %2;" : "=l"(d) : "l"(a), "l"(b)); return d;
}
static __device__ __forceinline__ float fast_ex2(float x) {
    float r; asm("ex2.approx.f32 %0, %1;" : "=f"(r) : "f"(x)); return r;
}

__global__ void k_pad() { g_pad = 0.0f; }

template <int PASS>
__global__ __launch_bounds__(THREADS, 2) void k_pass(const float* __restrict__ X,
                                                     const float* __restrict__ W) {
    extern __shared__ float smem[];
    float* s_x = smem;                 // [lb][r] stride SX_STRIDE
    float* s_w = smem + SX_SZ;         // 2 x 1280
    float* s_e = s_w + SW_SZ;          // 2 x (32*11)

    const int tid = threadIdx.x;
    const int n   = tid >> 5;          // warp id = n
    const int l   = tid & 31;          // lane
    const int bb  = l & 15;
    const int dh  = l >> 4;            // d-half
    const int cb  = blockIdx.x;        // i-chunk
    const int bh  = blockIdx.y;        // batch half
    int i0, ni;
    if (cb < 100) { i0 = cb * 28; ni = 28; }
    else          { i0 = 2800 + (cb - 100) * 27; ni = 27; }
    const int b1 = bh * 32 + bb;       // global batches for this thread
    const int b2 = b1 + 16;

    // ---- stage x: rows = 32 local batches, ni*8 floats each
    {
        int nr = ni * 8;
        for (int idx = tid; idx < 32 * nr; idx += THREADS) {
            int lb = idx / nr;
            int r  = idx - lb * nr;
            s_x[lb * SX_STRIDE + r] = X[(size_t)(bh * 32 + lb) * (I_ * P_) + i0 * P_ + r];
        }
    }
    // ---- stage W(0)
    *(float4*)(s_w + tid * 4) = *(const float4*)(W + (size_t)i0 * 1280 + tid * 4);

    // ---- v (log2-scaled) for both batches, this thread's d-half
    ull v2a[4], v2b[4];
    if (PASS > 0) {
        const float4* va = (const float4*)(g_v + b1 * ND_ + n * D_ + dh * 8);
        const float4* vb = (const float4*)(g_v + b2 * ND_ + n * D_ + dh * 8);
        float4 a0 = va[0], a1 = va[1], c0 = vb[0], c1 = vb[1];
        v2a[0] = pack2(a0.x * L2E, a0.y * L2E); v2a[1] = pack2(a0.z * L2E, a0.w * L2E);
        v2a[2] = pack2(a1.x * L2E, a1.y * L2E); v2a[3] = pack2(a1.z * L2E, a1.w * L2E);
        v2b[0] = pack2(c0.x * L2E, c0.y * L2E); v2b[1] = pack2(c0.z * L2E, c0.w * L2E);
        v2b[2] = pack2(c1.x * L2E, c1.y * L2E); v2b[3] = pack2(c1.z * L2E, c1.w * L2E);
    }
    __syncthreads();

    ull t2a[4], t2b[4], sa[4], sb[4];
#pragma unroll
    for (int j = 0; j < 4; j++) { sa[j] = 0ULL; sb[j] = 0ULL; }
    float e1p = 0.f, e2p = 0.f;

    for (int il = 0; il < ni; il++) {
        const int cur = il & 1;

        // ---- prefetches
        float4 wpf;
        bool wok = (il + 1 < ni);
        if (wok) wpf = *(const float4*)(W + (size_t)(i0 + il + 1) * 1280 + tid * 4);
        float gb1 = 0.f, gb2 = 0.f;
        if (PASS == 2) {
            float go = g_blog[(size_t)(i0 + il) * 640 + n * 64 + bh * 32 + l];
            float gt = __shfl_xor_sync(0xffffffffu, go, 16);
            gb1 = dh ? gt : go;
            gb2 = dh ? go : gt;
        }

        // ---- consume stage il-1 (t2 holds t(il-1); e(il-1) complete in s_e)
        if (il > 0) {
            if (PASS > 0) {
                const float* se = s_e + (1 - cur) * 352 + l * 11;   // conflict-free row
                float Z = ((se[0] + se[1]) + (se[2] + se[3])) +
                          ((se[4] + se[5]) + (se[6] + se[7])) + (se[8] + se[9]);
                float Zo = __shfl_xor_sync(0xffffffffu, Z, 16);
                float Z1 = dh ? Zo : Z;
                float Z2 = dh ? Z : Zo;
                float c1 = __fdividef(e1p, Z1);
                float c2 = __fdividef(e2p, Z2);
                ull cp1 = pack2(c1, c1), cp2 = pack2(c2, c2);
#pragma unroll
                for (int j = 0; j < 4; j++) {
                    sa[j] = ffma2(cp1, t2a[j], sa[j]);
                    sb[j] = ffma2(cp2, t2b[j], sb[j]);
                }
            } else {
#pragma unroll
                for (int j = 0; j < 4; j++) {
                    sa[j] = fadd2(sa[j], t2a[j]);
                    sb[j] = fadd2(sb[j], t2b[j]);
                }
            }
        }

        // ---- x for il (both batches): 2 x LDS.128 each
        float xa[8], xb[8];
        {
            const float4* xra = (const float4*)(s_x + bb * SX_STRIDE + il * 8);
            const float4* xrb = (const float4*)(s_x + (bb + 16) * SX_STRIDE + il * 8);
            float4 a0 = xra[0], a1 = xra[1], c0 = xrb[0], c1 = xrb[1];
            xa[0] = a0.x; xa[1] = a0.y; xa[2] = a0.z; xa[3] = a0.w;
            xa[4] = a1.x; xa[5] = a1.y; xa[6] = a1.z; xa[7] = a1.w;
            xb[0] = c0.x; xb[1] = c0.y; xb[2] = c0.z; xb[3] = c0.w;
            xb[4] = c1.x; xb[5] = c1.y; xb[6] = c1.z; xb[7] = c1.w;
        }

        // ---- t = u[b, i, n, d-half] for both batches
#pragma unroll
        for (int j = 0; j < 4; j++) { t2a[j] = 0ULL; t2b[j] = 0ULL; }
        {
            const float* wb = s_w + cur * 1280 + n * 128 + dh * 8;
#pragma unroll
            for (int p = 0; p < P_; p++) {
                ull xpa = pack2(xa[p], xa[p]);
                ull xpb = pack2(xb[p], xb[p]);
                ulonglong2 w0 = *(const ulonglong2*)(wb + p * 16);
                ulonglong2 w1 = *(const ulonglong2*)(wb + p * 16 + 4);
                t2a[0] = ffma2(xpa, w0.x, t2a[0]); t2a[1] = ffma2(xpa, w0.y, t2a[1]);
                t2a[2] = ffma2(xpa, w1.x, t2a[2]); t2a[3] = ffma2(xpa, w1.y, t2a[3]);
                t2b[0] = ffma2(xpb, w0.x, t2b[0]); t2b[1] = ffma2(xpb, w0.y, t2b[1]);
                t2b[2] = ffma2(xpb, w1.x, t2b[2]); t2b[3] = ffma2(xpb, w1.y, t2b[3]);
            }
        }

        // ---- produce: agreement (d-half partial + shfl), logits, exp
        if (PASS > 0) {
            ull aa = 0ULL, ab = 0ULL;
#pragma unroll
            for (int j = 0; j < 4; j++) {
                aa = ffma2(t2a[j], v2a[j], aa);
                ab = ffma2(t2b[j], v2b[j], ab);
            }
            float2 fa = unpack2(aa); float pa = fa.x + fa.y;
            float2 fb = unpack2(ab); float pb = fb.x + fb.y;
            float pao = __shfl_xor_sync(0xffffffffu, pa, 16);
            float pbo = __shfl_xor_sync(0xffffffffu, pb, 16);
            float bn1 = pa + pao + gb1;
            float bn2 = pb + pbo + gb2;
            if (PASS == 1)
                g_blog[(size_t)(i0 + il) * 640 + n * 64 + bh * 32 + l] = dh ? bn2 : bn1;
            e1p = fast_ex2(bn1);
            e2p = fast_ex2(bn2);
            s_e[cur * 352 + l * 11 + n] = dh ? e2p : e1p;   // lane l owns batch-row l
        }
        if (wok) *(float4*)(s_w + (1 - cur) * 1280 + tid * 4) = wpf;

        __syncthreads();
    }

    // ---- epilogue: consume last stage
    {
        const int prev = (ni - 1) & 1;
        if (PASS > 0) {
            const float* se = s_e + prev * 352 + l * 11;
            float Z = ((se[0] + se[1]) + (se[2] + se[3])) +
                      ((se[4] + se[5]) + (se[6] + se[7])) + (se[8] + se[9]);
            float Zo = __shfl_xor_sync(0xffffffffu, Z, 16);
            float Z1 = dh ? Zo : Z;
            float Z2 = dh ? Z : Zo;
            float c1 = __fdividef(e1p, Z1);
            float c2 = __fdividef(e2p, Z2);
            ull cp1 = pack2(c1, c1), cp2 = pack2(c2, c2);
#pragma unroll
            for (int j = 0; j < 4; j++) {
                sa[j] = ffma2(cp1, t2a[j], sa[j]);
                sb[j] = ffma2(cp2, t2b[j], sb[j]);
            }
        } else {
#pragma unroll
            for (int j = 0; j < 4; j++) {
                sa[j] = fadd2(sa[j], t2a[j]);
                sb[j] = fadd2(sb[j], t2b[j]);
            }
        }
    }

    // ---- per-chunk partials (deterministic)
    {
        float* p1 = g_part + (size_t)cb * OUT_ + b1 * ND_ + n * D_ + dh * 8;
        float* p2 = g_part + (size_t)cb * OUT_ + b2 * ND_ + n * D_ + dh * 8;
        float2 a0 = unpack2(sa[0]), a1 = unpack2(sa[1]);
        float2 a2 = unpack2(sa[2]), a3 = unpack2(sa[3]);
        float2 c0 = unpack2(sb[0]), c1 = unpack2(sb[1]);
        float2 c2 = unpack2(sb[2]), c3 = unpack2(sb[3]);
        float k = (PASS == 0) ? 0.1f : 1.0f;
        *(float4*)(p1)     = make_float4(a0.x * k, a0.y * k, a1.x * k, a1.y * k);
        *(float4*)(p1 + 4) = make_float4(a2.x * k, a2.y * k, a3.x * k, a3.y * k);
        *(float4*)(p2)     = make_float4(c0.x * k, c0.y * k, c1.x * k, c1.y * k);
        *(float4*)(p2 + 4) = make_float4(c2.x * k, c2.y * k, c3.x * k, c3.y * k);
    }
}

// 148-way reduction + squash. Grid 320 x 512: 16 slices (4x10 + 12x9 = 148).
template <bool FINAL>
__global__ __launch_bounds__(512) void k_finish(float* __restrict__ dout) {
    __shared__ float red[16][33];
    int tid = threadIdx.x;
    int s = tid >> 5;
    int ol = tid & 31;
    int o = blockIdx.x * 32 + ol;

    int start = (s < 4) ? s * 10 : 40 + (s - 4) * 9;
    int cnt = (s < 4) ? 10 : 9;
    const float* p = g_part + (size_t)start * OUT_ + o;
    float a0 = 0.f, a1 = 0.f, a2 = 0.f, a3 = 0.f;
    int k = 0;
    for (; k + 4 <= cnt; k += 4) {
        a0 += p[(size_t)(k + 0) * OUT_];
        a1 += p[(size_t)(k + 1) * OUT_];
        a2 += p[(size_t)(k + 2) * OUT_];
        a3 += p[(size_t)(k + 3) * OUT_];
    }
    for (; k < cnt; k++) a0 += p[(size_t)k * OUT_];
    red[s][ol] = (a0 + a1) + (a2 + a3);
    __syncthreads();

    if (s == 0) {
        float t0 = (red[0][ol] + red[1][ol]) + (red[2][ol] + red[3][ol]);
        float t1 = (red[4][ol] + red[5][ol]) + (red[6][ol] + red[7][ol]);
        float t2 = (red[8][ol] + red[9][ol]) + (red[10][ol] + red[11][ol]);
        float t3 = (red[12][ol] + red[13][ol]) + (red[14][ol] + red[15][ol]);
        float sv = (t0 + t1) + (t2 + t3);
        float sq = sv * sv;
        float scale = sq / ((1.f + sq) * sqrtf(sq + 1e-7f));
        float v = scale * sv;
        if (FINAL) dout[o] = v;
        else       g_v[o] = v;
    }
}

extern "C" void kernel_launch(void* const* d_in, const int* in_sizes, int n_in,
                              void* d_out, int out_size) {
    const float* X = (const float*)d_in[0];
    const float* W = (const float*)d_in[1];
    if (n_in >= 2 && in_sizes[0] != B_ * I_ * P_) {
        const float* tmp = X; X = W; W = tmp;
    }

    dim3 gp(148, 2);
    k_pad<<<1, 1>>>();
    k_pass<0><<<gp, THREADS, SMEM_BYTES>>>(X, W);
    k_finish<false><<<320, 512>>>(nullptr);
    k_pass<1><<<gp, THREADS, SMEM_BYTES>>>(X, W);
    k_finish<false><<<320, 512>>>(nullptr);
    k_pass<2><<<gp, THREADS, SMEM_BYTES>>>(X, W);
    k_finish<true><<<320, 512>>>((float*)d_out);
}